// round 4
// baseline (speedup 1.0000x reference)
#include <cuda_runtime.h>
#include <cuda_bf16.h>

// ---------------------------------------------------------------------------
// BSplineBasis: out[N,6] = cubic B-spline basis of min-max-normalized x.
// Knots compile-time => each span's 4 nonzero bases are closed-form cubics
// with exact-fp32 dyadic coefficients (Horner, 4 independent 3-FMA chains).
// Kernel 1: min/max reduction -> g_norm = {scale, -xmin*scale}.
// Kernel 2: 8 pts/thread, span-specialized polynomial eval, streaming stores.
// ---------------------------------------------------------------------------

#define MAXB 1184
#define K13 0.33333334f   /* fp32(1/3) */
#define K23 0.6666667f    /* fp32(2/3) */

__device__ unsigned g_pmin[MAXB];
__device__ unsigned g_pmax[MAXB];
__device__ unsigned g_count = 0;     // restored to 0 each run (graph-safe)
__device__ float2   g_norm;          // {scale, nbias = -xmin*scale}

__device__ __forceinline__ unsigned fenc(float f) {
    unsigned u = __float_as_uint(f);
    return (u & 0x80000000u) ? ~u : (u | 0x80000000u);
}
__device__ __forceinline__ float fdec(unsigned u) {
    return (u & 0x80000000u) ? __uint_as_float(u ^ 0x80000000u)
                             : __uint_as_float(~u);
}

__global__ void __launch_bounds__(256)
reduce_setup_kernel(const float* __restrict__ x, int n)
{
    float lmin =  3.4e38f, lmax = -3.4e38f;

    int n4 = n >> 2;
    const float4* __restrict__ x4 = (const float4*)x;
    int stride = gridDim.x * blockDim.x;
    #pragma unroll 4
    for (int i = blockIdx.x * blockDim.x + threadIdx.x; i < n4; i += stride) {
        float4 v = x4[i];
        lmin = fminf(lmin, fminf(fminf(v.x, v.y), fminf(v.z, v.w)));
        lmax = fmaxf(lmax, fmaxf(fmaxf(v.x, v.y), fmaxf(v.z, v.w)));
    }
    for (int i = n4 * 4 + blockIdx.x * blockDim.x + threadIdx.x; i < n; i += stride) {
        float e = x[i];
        lmin = fminf(lmin, e); lmax = fmaxf(lmax, e);
    }

    unsigned emin = __reduce_min_sync(0xFFFFFFFFu, fenc(lmin));
    unsigned emax = __reduce_max_sync(0xFFFFFFFFu, fenc(lmax));

    __shared__ unsigned smin[8], smax[8];
    __shared__ bool is_last;
    int w = threadIdx.x >> 5;
    if ((threadIdx.x & 31) == 0) { smin[w] = emin; smax[w] = emax; }
    __syncthreads();
    if (threadIdx.x == 0) {
        int nw = blockDim.x >> 5;
        for (int i = 1; i < nw; i++) {
            emin = min(emin, smin[i]); emax = max(emax, smax[i]);
        }
        g_pmin[blockIdx.x] = emin;
        g_pmax[blockIdx.x] = emax;
        __threadfence();
        unsigned prev = atomicAdd(&g_count, 1u);
        is_last = (prev == gridDim.x - 1);
    }
    __syncthreads();
    if (!is_last) return;

    unsigned fmn = 0xFFFFFFFFu, fmx = 0u;
    int nb = gridDim.x;
    for (int i = threadIdx.x; i < nb; i += blockDim.x) {
        fmn = min(fmn, __ldcg(&g_pmin[i]));
        fmx = max(fmx, __ldcg(&g_pmax[i]));
    }
    fmn = __reduce_min_sync(0xFFFFFFFFu, fmn);
    fmx = __reduce_max_sync(0xFFFFFFFFu, fmx);
    if ((threadIdx.x & 31) == 0) { smin[w] = fmn; smax[w] = fmx; }
    __syncthreads();
    if (threadIdx.x == 0) {
        int nw = blockDim.x >> 5;
        for (int i = 1; i < nw; i++) {
            fmn = min(fmn, smin[i]); fmx = max(fmx, smax[i]);
        }
        float xmin = fdec(fmn);
        float xmax = fdec(fmx);
        float scale = 1.0f / (xmax - xmin + 1e-8f);
        g_norm = make_float2(scale, -xmin * scale);
        __threadfence();
        g_count = 0;
    }
}

// Closed-form cubic bases per span; coefficients are exact fp32 dyadics.
__device__ __forceinline__ void evalPoint(float u, float* __restrict__ o)
{
    if (u < K13) {
        // span0: bases 0..3
        float N0 = fmaf(u, -27.0f, 27.0f);  N0 = fmaf(u, N0, -9.0f);  N0 = fmaf(u, N0, 1.0f);
        float N1 = fmaf(u, 47.25f, -40.5f); N1 = fmaf(u, N1, 9.0f);   N1 = N1 * u;
        float N2 = fmaf(u, -24.75f, 13.5f); N2 = N2 * (u * u);
        float N3 = 4.5f * u * (u * u);
        o[0] = N0; o[1] = N1; o[2] = N2; o[3] = N3; o[4] = 0.0f; o[5] = 0.0f;
    } else if (u < K23) {
        // span1: bases 1..4
        float N1 = fmaf(u, -6.75f, 13.5f);   N1 = fmaf(u, N1, -9.0f);  N1 = fmaf(u, N1, 2.0f);
        float N2 = fmaf(u, 15.75f, -27.0f);  N2 = fmaf(u, N2, 13.5f);  N2 = fmaf(u, N2, -1.5f);
        float N3 = fmaf(u, -15.75f, 20.25f); N3 = fmaf(u, N3, -6.75f); N3 = fmaf(u, N3, 0.75f);
        float N4 = fmaf(u, 6.75f, -6.75f);   N4 = fmaf(u, N4, 2.25f);  N4 = fmaf(u, N4, -0.25f);
        o[0] = 0.0f; o[1] = N1; o[2] = N2; o[3] = N3; o[4] = N4; o[5] = 0.0f;
    } else {
        // span2 = mirror of span0 in w = 1-u: bases 2..5
        float w = 1.0f - u;
        float N5 = fmaf(w, -27.0f, 27.0f);  N5 = fmaf(w, N5, -9.0f);  N5 = fmaf(w, N5, 1.0f);
        float N4 = fmaf(w, 47.25f, -40.5f); N4 = fmaf(w, N4, 9.0f);   N4 = N4 * w;
        float N3 = fmaf(w, -24.75f, 13.5f); N3 = N3 * (w * w);
        float N2 = 4.5f * w * (w * w);
        o[0] = 0.0f; o[1] = 0.0f; o[2] = N2; o[3] = N3; o[4] = N4; o[5] = N5;
    }
}

__global__ void __launch_bounds__(256)
bspline_main_kernel(const float* __restrict__ x,
                    float* __restrict__ out, int n)
{
    int tid = blockIdx.x * blockDim.x + threadIdx.x;
    int base = tid * 8;
    if (base >= n) return;

    float2 nrm = g_norm;
    float scale = nrm.x, nb = nrm.y;

    if (base + 8 <= n) {
        const float4* __restrict__ x4 = (const float4*)x;
        float4 va = x4[2 * tid];        // MLP=2: both loads issued up front
        float4 vb = x4[2 * tid + 1];
        float xs[8] = {va.x, va.y, va.z, va.w, vb.x, vb.y, vb.z, vb.w};

        float4* o4 = (float4*)(out + (size_t)base * 6);
        #pragma unroll
        for (int h = 0; h < 2; h++) {
            float res[24];
            #pragma unroll
            for (int p = 0; p < 4; p++) {
                float u = fmaf(xs[h * 4 + p], scale, nb);
                evalPoint(u, &res[p * 6]);
            }
            #pragma unroll
            for (int v = 0; v < 6; v++)
                __stcs(o4 + h * 6 + v,
                       make_float4(res[4 * v], res[4 * v + 1],
                                   res[4 * v + 2], res[4 * v + 3]));
        }
    } else {
        // scalar tail
        for (int p = 0; p < 8 && base + p < n; p++) {
            float u = fmaf(x[base + p], scale, nb);
            float b6[6];
            evalPoint(u, b6);
            float* o = out + (size_t)(base + p) * 6;
            #pragma unroll
            for (int j = 0; j < 6; j++) o[j] = b6[j];
        }
    }
}

extern "C" void kernel_launch(void* const* d_in, const int* in_sizes, int n_in,
                              void* d_out, int out_size)
{
    const float* x = (const float*)d_in[0];
    float* out     = (float*)d_out;
    int n = in_sizes[0];
    if (n <= 0) return;

    int n4 = n >> 2;
    int rblocks = (n4 + 255) / 256;
    if (rblocks > MAXB) rblocks = MAXB;
    if (rblocks < 1) rblocks = 1;
    reduce_setup_kernel<<<rblocks, 256>>>(x, n);

    int nthreads_total = (n + 7) / 8;
    int mblocks = (nthreads_total + 255) / 256;
    bspline_main_kernel<<<mblocks, 256>>>(x, out, n);
}

// round 5
// speedup vs baseline: 1.9880x; 1.9880x over previous
#include <cuda_runtime.h>
#include <cuda_bf16.h>

// ---------------------------------------------------------------------------
// BSplineBasis: out[N,6] = cubic B-spline basis of min-max-normalized x.
// Knots compile-time ([0,0,0,0,1/3,2/3,1,1,1,1]) => closed-form span cubics.
// Kernel 1: min/max reduction -> g_norm = {scale, -xmin*scale}.
// Kernel 2: 4 pts/thread, polynomial eval, per-warp smem transpose so all
//           global stores are lane-contiguous STG.128 (4 lines/instr).
// ---------------------------------------------------------------------------

#define MAXB 1184
#define K13 0.33333334f   /* fp32(1/3) */
#define K23 0.6666667f    /* fp32(2/3) */

__device__ unsigned g_pmin[MAXB];
__device__ unsigned g_pmax[MAXB];
__device__ unsigned g_count = 0;     // restored to 0 each run (graph-safe)
__device__ float2   g_norm;          // {scale, nbias = -xmin*scale}

__device__ __forceinline__ unsigned fenc(float f) {
    unsigned u = __float_as_uint(f);
    return (u & 0x80000000u) ? ~u : (u | 0x80000000u);
}
__device__ __forceinline__ float fdec(unsigned u) {
    return (u & 0x80000000u) ? __uint_as_float(u ^ 0x80000000u)
                             : __uint_as_float(~u);
}

__global__ void __launch_bounds__(256)
reduce_setup_kernel(const float* __restrict__ x, int n)
{
    float lmin =  3.4e38f, lmax = -3.4e38f;

    int n4 = n >> 2;
    const float4* __restrict__ x4 = (const float4*)x;
    int stride = gridDim.x * blockDim.x;
    #pragma unroll 4
    for (int i = blockIdx.x * blockDim.x + threadIdx.x; i < n4; i += stride) {
        float4 v = x4[i];
        lmin = fminf(lmin, fminf(fminf(v.x, v.y), fminf(v.z, v.w)));
        lmax = fmaxf(lmax, fmaxf(fmaxf(v.x, v.y), fmaxf(v.z, v.w)));
    }
    for (int i = n4 * 4 + blockIdx.x * blockDim.x + threadIdx.x; i < n; i += stride) {
        float e = x[i];
        lmin = fminf(lmin, e); lmax = fmaxf(lmax, e);
    }

    unsigned emin = __reduce_min_sync(0xFFFFFFFFu, fenc(lmin));
    unsigned emax = __reduce_max_sync(0xFFFFFFFFu, fenc(lmax));

    __shared__ unsigned smin[8], smax[8];
    __shared__ bool is_last;
    int w = threadIdx.x >> 5;
    if ((threadIdx.x & 31) == 0) { smin[w] = emin; smax[w] = emax; }
    __syncthreads();
    if (threadIdx.x == 0) {
        int nw = blockDim.x >> 5;
        for (int i = 1; i < nw; i++) {
            emin = min(emin, smin[i]); emax = max(emax, smax[i]);
        }
        g_pmin[blockIdx.x] = emin;
        g_pmax[blockIdx.x] = emax;
        __threadfence();
        unsigned prev = atomicAdd(&g_count, 1u);
        is_last = (prev == gridDim.x - 1);
    }
    __syncthreads();
    if (!is_last) return;

    unsigned fmn = 0xFFFFFFFFu, fmx = 0u;
    int nb = gridDim.x;
    for (int i = threadIdx.x; i < nb; i += blockDim.x) {
        fmn = min(fmn, __ldcg(&g_pmin[i]));
        fmx = max(fmx, __ldcg(&g_pmax[i]));
    }
    fmn = __reduce_min_sync(0xFFFFFFFFu, fmn);
    fmx = __reduce_max_sync(0xFFFFFFFFu, fmx);
    if ((threadIdx.x & 31) == 0) { smin[w] = fmn; smax[w] = fmx; }
    __syncthreads();
    if (threadIdx.x == 0) {
        int nw = blockDim.x >> 5;
        for (int i = 1; i < nw; i++) {
            fmn = min(fmn, smin[i]); fmx = max(fmx, smax[i]);
        }
        float xmin = fdec(fmn);
        float xmax = fdec(fmx);
        float scale = 1.0f / (xmax - xmin + 1e-8f);
        g_norm = make_float2(scale, -xmin * scale);
        __threadfence();
        g_count = 0;
    }
}

// Closed-form cubic bases per span; coefficients are exact fp32 dyadics.
__device__ __forceinline__ void evalPoint(float u, float* __restrict__ o)
{
    if (u < K13) {
        float N0 = fmaf(u, -27.0f, 27.0f);  N0 = fmaf(u, N0, -9.0f);  N0 = fmaf(u, N0, 1.0f);
        float N1 = fmaf(u, 47.25f, -40.5f); N1 = fmaf(u, N1, 9.0f);   N1 = N1 * u;
        float N2 = fmaf(u, -24.75f, 13.5f); N2 = N2 * (u * u);
        float N3 = 4.5f * u * (u * u);
        o[0] = N0; o[1] = N1; o[2] = N2; o[3] = N3; o[4] = 0.0f; o[5] = 0.0f;
    } else if (u < K23) {
        float N1 = fmaf(u, -6.75f, 13.5f);   N1 = fmaf(u, N1, -9.0f);  N1 = fmaf(u, N1, 2.0f);
        float N2 = fmaf(u, 15.75f, -27.0f);  N2 = fmaf(u, N2, 13.5f);  N2 = fmaf(u, N2, -1.5f);
        float N3 = fmaf(u, -15.75f, 20.25f); N3 = fmaf(u, N3, -6.75f); N3 = fmaf(u, N3, 0.75f);
        float N4 = fmaf(u, 6.75f, -6.75f);   N4 = fmaf(u, N4, 2.25f);  N4 = fmaf(u, N4, -0.25f);
        o[0] = 0.0f; o[1] = N1; o[2] = N2; o[3] = N3; o[4] = N4; o[5] = 0.0f;
    } else {
        float w = 1.0f - u;
        float N5 = fmaf(w, -27.0f, 27.0f);  N5 = fmaf(w, N5, -9.0f);  N5 = fmaf(w, N5, 1.0f);
        float N4 = fmaf(w, 47.25f, -40.5f); N4 = fmaf(w, N4, 9.0f);   N4 = N4 * w;
        float N3 = fmaf(w, -24.75f, 13.5f); N3 = N3 * (w * w);
        float N2 = 4.5f * w * (w * w);
        o[0] = 0.0f; o[1] = 0.0f; o[2] = N2; o[3] = N3; o[4] = N4; o[5] = N5;
    }
}

// Per-warp staging: 32 lanes x 6 float4, padded to stride 7 per lane.
// Logical warp float4 index L (0..191) -> physical slot L + L/6.
// Write phase (L = 6*lane + v -> slot 7*lane + v): conflict-free.
// Read phase (L = v*32 + lane): lane-bijective per quarter-warp (rare 2-way).
#define WSTAGE 224

__global__ void __launch_bounds__(256)
bspline_main_kernel(const float* __restrict__ x,
                    float* __restrict__ out, int n)
{
    __shared__ float4 stage[8][WSTAGE];

    int lane = threadIdx.x & 31;
    int warp = threadIdx.x >> 5;
    int gwarp = blockIdx.x * 8 + warp;
    int wbase = gwarp * 128;             // first point of this warp
    if (wbase >= n) return;

    float2 nrm = g_norm;
    float scale = nrm.x, nb = nrm.y;

    if (wbase + 128 <= n) {
        // lane handles points wbase + 4*lane .. +3 (coalesced LDG.128)
        float4 v = ((const float4*)x)[(wbase >> 2) + lane];
        float xs[4] = {v.x, v.y, v.z, v.w};

        float res[24];
        #pragma unroll
        for (int p = 0; p < 4; p++) {
            float u = fmaf(xs[p], scale, nb);
            evalPoint(u, &res[p * 6]);
        }

        float4* ws = stage[warp];
        #pragma unroll
        for (int q = 0; q < 6; q++)
            ws[7 * lane + q] = make_float4(res[4 * q], res[4 * q + 1],
                                           res[4 * q + 2], res[4 * q + 3]);
        __syncwarp();

        // coalesced streaming stores: 6 x STG.128, 16-B lane stride
        float4* o4 = (float4*)out + (size_t)wbase * 6 / 4;
        #pragma unroll
        for (int q = 0; q < 6; q++) {
            int L = q * 32 + lane;
            __stcs(o4 + L, ws[L + L / 6]);
        }
    } else {
        // tail warp: scalar per-point
        for (int p = lane; p < 128; p += 32) {
            int idx = wbase + p;
            if (idx >= n) break;
            float u = fmaf(x[idx], scale, nb);
            float b6[6];
            evalPoint(u, b6);
            float* o = out + (size_t)idx * 6;
            #pragma unroll
            for (int j = 0; j < 6; j++) o[j] = b6[j];
        }
    }
}

extern "C" void kernel_launch(void* const* d_in, const int* in_sizes, int n_in,
                              void* d_out, int out_size)
{
    const float* x = (const float*)d_in[0];
    float* out     = (float*)d_out;
    int n = in_sizes[0];
    if (n <= 0) return;

    int n4 = n >> 2;
    int rblocks = (n4 + 255) / 256;
    if (rblocks > MAXB) rblocks = MAXB;
    if (rblocks < 1) rblocks = 1;
    reduce_setup_kernel<<<rblocks, 256>>>(x, n);

    int npts_per_block = 1024;           // 8 warps * 128 pts
    int mblocks = (n + npts_per_block - 1) / npts_per_block;
    bspline_main_kernel<<<mblocks, 256>>>(x, out, n);
}